// round 4
// baseline (speedup 1.0000x reference)
#include <cuda_runtime.h>
#include <cstdint>
#include <cstddef>

// HugeNet: 10000 x (Linear(100,100)+ReLU) scan, then Linear(100,10).
//
// Round 4: 512 threads/CTA (16 warps -> latency hiding), 8-way k-split,
// J=2 cols/thread, fully-parallel 2-phase reduction, W streamed to regs
// from a thread-interleaved fp32 gmem layout. 64 CTAs x 4 rows.
//
// Phase-1 thread (m = tid&63, kq = tid>>6):
//   cols j0=2m, j1=2m+1 (m<50 useful); k-range base {0,16,28,...,88}, 4|3 quads
// Phase-2 thread (i = tid>>6, m = tid&63):
//   output (row r = i&3, col j = 2m + (i>>2)); sums 8 partials.

#define N_LAYERS 10000
#define D        100
#define D_OUT    10
#define BATCH    256
#define ROWS     4
#define NCTA     (BATCH / ROWS)   // 64
#define THREADS  512
#define KQ       8
#define WSLOTS   8                // max float4 per thread per layer (kq0: 2*4)

typedef unsigned long long ull;

// [(N_LAYERS+2)][WSLOTS][512] float4  (~655MB, zero-padded)
__device__ __align__(16) float4 g_Wp[(size_t)(N_LAYERS + 2) * WSLOTS * THREADS];

__host__ __device__ __forceinline__ int kq_base(int kq) {
    return (kq == 0) ? 0 : (16 + 12 * (kq - 1));   // {0,16,28,40,52,64,76,88}
}
__host__ __device__ __forceinline__ int kq_nq(int kq) {
    return (kq == 0) ? 4 : 3;
}

// ---------------------------------------------------------------------------
// prep: W[l][j][k] row-major -> g_Wp[((l*WSLOTS)+i)*512 + t]
//   t -> (m = t&63, kq = t>>6); i = 2q+jj; j = 2m+jj; k = kq_base(kq)+4q
// ---------------------------------------------------------------------------
__global__ void prep_kernel(const float* __restrict__ W) {
    size_t idx = (size_t)blockIdx.x * blockDim.x + threadIdx.x;
    const size_t total = (size_t)(N_LAYERS + 2) * WSLOTS * THREADS;
    if (idx >= total) return;
    int    t    = (int)(idx & (THREADS - 1));
    size_t rest = idx >> 9;
    int    i    = (int)(rest & (WSLOTS - 1));
    size_t l    = rest >> 3;
    int m  = t & 63, kq = t >> 6;
    int jj = i & 1,  q  = i >> 1;
    int j  = 2 * m + jj;
    int k  = kq_base(kq) + 4 * q;
    float4 v = make_float4(0.f, 0.f, 0.f, 0.f);
    if (l < N_LAYERS && j < D && q < kq_nq(kq))
        v = *reinterpret_cast<const float4*>(
                W + l * (size_t)(D * D) + (size_t)j * D + k);
    g_Wp[idx] = v;
}

// ---------------------------------------------------------------------------
__device__ __forceinline__ void fma2(ull& a, ull x, ull y) {
    asm("fma.rn.f32x2 %0, %1, %2, %0;" : "+l"(a) : "l"(x), "l"(y));
}
__device__ __forceinline__ float2 upk(ull v) {
    float2 r;
    asm("mov.b64 {%0, %1}, %2;" : "=f"(r.x), "=f"(r.y) : "l"(v));
    return r;
}

__global__ void __launch_bounds__(THREADS, 1)
hugenet_kernel(const float* __restrict__ x,
               const float* __restrict__ bg,
               const float* __restrict__ Wo,
               const float* __restrict__ bo,
               float* __restrict__ out) {
    __shared__ float h[2][ROWS][D];       // 3.2KB, rows 400B (16B-mult) stride
    __shared__ float red[KQ][8][64];      // 16KB, conflict-free both phases

    const int tid = threadIdx.x;
    const int m   = tid & 63;             // phase-1 column pair
    const int kq  = tid >> 6;             // phase-1 k-group
    const int nq  = kq_nq(kq);
    const int kb  = kq_base(kq);
    const int i2  = tid >> 6;             // phase-2 (jj*4+r)
    const int m2  = tid & 63;             // phase-2 column pair
    const int r2  = i2 & 3;
    const int j2  = 2 * m2 + (i2 >> 2);   // phase-2 output column
    const int r0  = blockIdx.x * ROWS;

    for (int idx = tid; idx < ROWS * D; idx += THREADS) {
        int r = idx / D, k = idx % D;
        h[0][r][k] = x[(size_t)(r0 + r) * D + k];
    }
    __syncthreads();

    float4 Wa[WSLOTS], Wb[WSLOTS];

    auto ldW = [&](float4* R, int l) {
        const float4* p = g_Wp + (size_t)l * WSLOTS * THREADS + tid;
        #pragma unroll
        for (int i = 0; i < WSLOTS; i++)
            if (i < 2 * nq) R[i] = __ldg(p + (size_t)i * THREADS);
    };

    float bias_a = 0.f, bias_b = 0.f;
    auto ldB = [&](float& bb, int l) {
        if (m2 < 50 && l < N_LAYERS)
            bb = __ldg(bg + (size_t)l * D + j2);
    };

    auto do_layer = [&](const float4* R, float bias, int HB) {
        // ---- phase 1: partial dot products over this thread's k-group ----
        ull a[8];
        #pragma unroll
        for (int i = 0; i < 8; i++) a[i] = 0ull;

        #pragma unroll
        for (int q = 0; q < 4; q++) {
            if (q < nq) {
                ulonglong2 w0 = *reinterpret_cast<const ulonglong2*>(&R[2 * q]);
                ulonglong2 w1 = *reinterpret_cast<const ulonglong2*>(&R[2 * q + 1]);
                #pragma unroll
                for (int r = 0; r < ROWS; r++) {
                    ulonglong2 hv =
                        *reinterpret_cast<const ulonglong2*>(&h[HB][r][kb + 4 * q]);
                    fma2(a[r],     hv.x, w0.x);
                    fma2(a[r],     hv.y, w0.y);
                    fma2(a[4 + r], hv.x, w1.x);
                    fma2(a[4 + r], hv.y, w1.y);
                }
            }
        }
        #pragma unroll
        for (int i = 0; i < 8; i++) {
            float2 u = upk(a[i]);
            red[kq][i][m] = u.x + u.y;
        }
        __syncthreads();

        // ---- phase 2: all 512 threads reduce + relu + write h ----
        float s = bias;
        #pragma unroll
        for (int g = 0; g < KQ; g++) s += red[g][i2][m2];
        if (m2 < 50)
            h[HB ^ 1][r2][j2] = fmaxf(s, 0.f);
        __syncthreads();
    };

    ldW(Wa, 0);
    ldB(bias_a, 0);

    #pragma unroll 1
    for (int l = 0; l < N_LAYERS; l += 2) {
        ldW(Wb, l + 1);
        ldB(bias_b, l + 1);

        do_layer(Wa, bias_a, 0);          // h[0] -> h[1]

        ldW(Wa, l + 2);                   // pad layers are zeroed
        ldB(bias_a, l + 2);

        do_layer(Wb, bias_b, 1);          // h[1] -> h[0]
    }

    // Final Linear(100, 10): 40 threads, one (row, out-col) each. h in h[0].
    if (tid < ROWS * D_OUT) {
        int r = tid / D_OUT, o = tid % D_OUT;
        const float* hr = h[0][r];
        float acc = bo[o];
        #pragma unroll
        for (int k = 0; k < D; k++)
            acc += hr[k] * __ldg(&Wo[(size_t)o * D + k]);
        out[(size_t)(r0 + r) * D_OUT + o] = acc;
    }
}

// ---------------------------------------------------------------------------
extern "C" void kernel_launch(void* const* d_in, const int* in_sizes, int n_in,
                              void* d_out, int out_size) {
    const float *x = nullptr, *W = nullptr, *b = nullptr, *Wo = nullptr, *bo = nullptr;
    for (int i = 0; i < n_in; i++) {
        switch (in_sizes[i]) {
            case 25600:     x  = (const float*)d_in[i]; break;
            case 100000000: W  = (const float*)d_in[i]; break;
            case 1000000:   b  = (const float*)d_in[i]; break;
            case 1000:      Wo = (const float*)d_in[i]; break;
            case 10:        bo = (const float*)d_in[i]; break;
            default: break;
        }
    }

    const size_t total = (size_t)(N_LAYERS + 2) * WSLOTS * THREADS;
    int blocks = (int)((total + 255) / 256);
    prep_kernel<<<blocks, 256>>>(W);

    hugenet_kernel<<<NCTA, THREADS>>>(x, b, Wo, bo, (float*)d_out);
}